// round 2
// baseline (speedup 1.0000x reference)
#include <cuda_runtime.h>
#include <math.h>

#define FULLMASK 0xffffffffu

// Scratch (device globals — no allocation allowed)
__device__ __align__(16) float g_gate[8][4];
__device__ __align__(16) float g_A[8][16384];       // [b][r*2048+d]
__device__ __align__(16) float g_B[8][16384];       // [b][r*2048+o], pre-scaled by 2.0
__device__ __align__(16) float g_xa[8][2048][8];    // [b][s][r]

union F2U { float2 f; unsigned long long u; };

__device__ __forceinline__ float2 ffma2(float2 a, float2 b, float2 c) {
    F2U ua, ub, uc, ur;
    ua.f = a; ub.f = b; uc.f = c;
    asm("fma.rn.f32x2 %0, %1, %2, %3;"
        : "=l"(ur.u) : "l"(ua.u), "l"(ub.u), "l"(uc.u));
    return ur.f;
}

// ---------------------------------------------------------------------------
// Kernel 1: gating MLP.  8 warps, warp w handles batch w.
// ---------------------------------------------------------------------------
__global__ void gate_kernel(const float* __restrict__ ctr,
                            const float* __restrict__ gamma,
                            const float* __restrict__ beta,
                            const float* __restrict__ W1,
                            const float* __restrict__ b1,
                            const float* __restrict__ W2,
                            const float* __restrict__ b2) {
    __shared__ float h_s[8][64];
    int w = threadIdx.x >> 5;
    int lane = threadIdx.x & 31;

    float c = ctr[w * 32 + lane];
    float mu = c;
    #pragma unroll
    for (int o = 16; o; o >>= 1) mu += __shfl_xor_sync(FULLMASK, mu, o);
    mu *= 0.03125f;
    float d = c - mu;
    float v = d * d;
    #pragma unroll
    for (int o = 16; o; o >>= 1) v += __shfl_xor_sync(FULLMASK, v, o);
    v *= 0.03125f;
    float z = d * rsqrtf(v + 1e-5f) * gamma[lane] + beta[lane];

    // h = relu(z @ W1^T + b1), 60 outputs; lanes cover j and j+32
    #pragma unroll
    for (int jj = 0; jj < 2; jj++) {
        int j = lane + (jj << 5);
        bool valid = (j < 60);
        float s = valid ? b1[j] : 0.f;
        for (int k = 0; k < 32; k++) {
            float zk = __shfl_sync(FULLMASK, z, k);   // all lanes participate
            if (valid) s += W1[j * 32 + k] * zk;
        }
        h_s[w][j] = valid ? fmaxf(s, 0.f) : 0.f;
    }
    __syncwarp();

    if (lane == 0) {
        float l[4], mx = -3.4e38f;
        #pragma unroll
        for (int i = 0; i < 4; i++) {
            float s = b2[i];
            for (int j = 0; j < 60; j++) s += W2[i * 60 + j] * h_s[w][j];
            l[i] = s;
            mx = fmaxf(mx, s);
        }
        float e[4], sum = 0.f;
        #pragma unroll
        for (int i = 0; i < 4; i++) { e[i] = expf(l[i] - mx); sum += e[i]; }
        float inv = 1.f / sum;
        #pragma unroll
        for (int i = 0; i < 4; i++) g_gate[w][i] = e[i] * inv;
    }
}

// ---------------------------------------------------------------------------
// Kernel 2: A = gate @ Wa^T, B = 2.0 * (gate @ Wb^T).  One thread per element.
// ---------------------------------------------------------------------------
__global__ void ab_kernel(const float4* __restrict__ Wa,
                          const float4* __restrict__ Wb) {
    int i = blockIdx.x * blockDim.x + threadIdx.x;   // 0 .. 262143
    int half = i >> 17;                              // 0: A, 1: B
    int j = i & 131071;
    int b = j >> 14;
    int idx = j & 16383;
    float4 g = *(const float4*)&g_gate[b][0];
    float4 wv = half ? Wb[idx] : Wa[idx];
    float v = g.x * wv.x + g.y * wv.y + g.z * wv.z + g.w * wv.w;
    if (half) g_B[b][idx] = v * 2.0f;                // SCALING = 16/8 folded here
    else      g_A[b][idx] = v;
}

// ---------------------------------------------------------------------------
// Kernel 3: xa[b][s][r] = sum_d x[b][s][d] * A[b][r][d]
// Block = (batch, 32 rows). A[b] in 64KB smem. Warp handles 4 rows so each
// A float4 LDS serves 4 rows. FFMA2-packed accumulation, warp reduce.
// ---------------------------------------------------------------------------
__global__ __launch_bounds__(256) void xa_kernel(const float* __restrict__ x) {
    extern __shared__ float4 A_s[];   // 4096 float4 = 64 KB
    int b = blockIdx.y;
    const float4* Ag = (const float4*)&g_A[b][0];
    for (int i = threadIdx.x; i < 4096; i += 256) A_s[i] = Ag[i];
    __syncthreads();

    int warp = threadIdx.x >> 5;
    int lane = threadIdx.x & 31;
    int row0 = blockIdx.x * 32 + warp * 4;
    const float4* xrow = (const float4*)(x + (((size_t)b << 11) + row0) * 2048);

    float2 acc[4][8];
    #pragma unroll
    for (int j = 0; j < 4; j++)
        #pragma unroll
        for (int r = 0; r < 8; r++) acc[j][r] = make_float2(0.f, 0.f);

    #pragma unroll 4
    for (int i = 0; i < 16; i++) {
        int d4 = (i << 5) + lane;
        float4 xv0 = xrow[d4];
        float4 xv1 = xrow[512 + d4];
        float4 xv2 = xrow[1024 + d4];
        float4 xv3 = xrow[1536 + d4];
        #pragma unroll
        for (int r = 0; r < 8; r++) {
            float4 av = A_s[(r << 9) + d4];
            float2 alo = make_float2(av.x, av.y);
            float2 ahi = make_float2(av.z, av.w);
            acc[0][r] = ffma2(make_float2(xv0.x, xv0.y), alo, acc[0][r]);
            acc[0][r] = ffma2(make_float2(xv0.z, xv0.w), ahi, acc[0][r]);
            acc[1][r] = ffma2(make_float2(xv1.x, xv1.y), alo, acc[1][r]);
            acc[1][r] = ffma2(make_float2(xv1.z, xv1.w), ahi, acc[1][r]);
            acc[2][r] = ffma2(make_float2(xv2.x, xv2.y), alo, acc[2][r]);
            acc[2][r] = ffma2(make_float2(xv2.z, xv2.w), ahi, acc[2][r]);
            acc[3][r] = ffma2(make_float2(xv3.x, xv3.y), alo, acc[3][r]);
            acc[3][r] = ffma2(make_float2(xv3.z, xv3.w), ahi, acc[3][r]);
        }
    }

    #pragma unroll
    for (int j = 0; j < 4; j++) {
        float s[8];
        #pragma unroll
        for (int r = 0; r < 8; r++) {
            float v = acc[j][r].x + acc[j][r].y;
            #pragma unroll
            for (int o = 16; o; o >>= 1) v += __shfl_xor_sync(FULLMASK, v, o);
            s[r] = v;
        }
        if (lane == 0) {
            float4* dst = (float4*)&g_xa[b][row0 + j][0];
            dst[0] = make_float4(s[0], s[1], s[2], s[3]);
            dst[1] = make_float4(s[4], s[5], s[6], s[7]);
        }
    }
}

// ---------------------------------------------------------------------------
// Kernel 4: out[b][s][o] = sum_r xa[b][s][r] * B[b][r][o]   (B pre-scaled)
// Block = (batch, 32 rows). Thread t owns cols [4t,4t+4) and [1024+4t,+4):
// B stays in registers, xa broadcast from smem, coalesced float4 stores.
// ---------------------------------------------------------------------------
__global__ __launch_bounds__(256) void out_kernel(float* __restrict__ out) {
    __shared__ float4 xa_s[64];       // 32 rows x 8 floats
    int b = blockIdx.y;
    int row0 = blockIdx.x * 32;
    int t = threadIdx.x;

    const float4* Bg = (const float4*)&g_B[b][0];  // [8][512] float4
    float4 B0[8], B1[8];
    #pragma unroll
    for (int r = 0; r < 8; r++) {
        B0[r] = Bg[(r << 9) + t];
        B1[r] = Bg[(r << 9) + 256 + t];
    }
    if (t < 64) xa_s[t] = ((const float4*)&g_xa[b][row0][0])[t];
    __syncthreads();

    float4* orow = (float4*)(out + (((size_t)b << 11) + row0) * 2048);
    #pragma unroll 2
    for (int row = 0; row < 32; row++) {
        float4 xa0 = xa_s[row * 2];
        float4 xa1 = xa_s[row * 2 + 1];
        float xr[8] = {xa0.x, xa0.y, xa0.z, xa0.w, xa1.x, xa1.y, xa1.z, xa1.w};
        float2 a0 = make_float2(0.f, 0.f), a1 = a0, a2 = a0, a3 = a0;
        #pragma unroll
        for (int r = 0; r < 8; r++) {
            float2 s = make_float2(xr[r], xr[r]);
            a0 = ffma2(s, make_float2(B0[r].x, B0[r].y), a0);
            a1 = ffma2(s, make_float2(B0[r].z, B0[r].w), a1);
            a2 = ffma2(s, make_float2(B1[r].x, B1[r].y), a2);
            a3 = ffma2(s, make_float2(B1[r].z, B1[r].w), a3);
        }
        orow[(row << 9) + t]       = make_float4(a0.x, a0.y, a1.x, a1.y);
        orow[(row << 9) + 256 + t] = make_float4(a2.x, a2.y, a3.x, a3.y);
    }
}

// ---------------------------------------------------------------------------
extern "C" void kernel_launch(void* const* d_in, const int* in_sizes, int n_in,
                              void* d_out, int out_size) {
    const float* x   = (const float*)d_in[0];
    const float* ctr = (const float*)d_in[1];
    const float* gam = (const float*)d_in[2];
    const float* bet = (const float*)d_in[3];
    const float* W1  = (const float*)d_in[4];
    const float* b1  = (const float*)d_in[5];
    const float* W2  = (const float*)d_in[6];
    const float* b2  = (const float*)d_in[7];
    const float* Wa  = (const float*)d_in[8];
    const float* Wb  = (const float*)d_in[9];
    float* out = (float*)d_out;

    cudaFuncSetAttribute(xa_kernel, cudaFuncAttributeMaxDynamicSharedMemorySize, 65536);

    gate_kernel<<<1, 256>>>(ctr, gam, bet, W1, b1, W2, b2);
    ab_kernel<<<1024, 256>>>((const float4*)Wa, (const float4*)Wb);
    xa_kernel<<<dim3(64, 8), 256, 65536>>>(x);
    out_kernel<<<dim3(64, 8), 256>>>(out);
}

// round 6
// speedup vs baseline: 1.2161x; 1.2161x over previous
#include <cuda_runtime.h>
#include <math.h>

#define FULLMASK 0xffffffffu

// Scratch (device globals — no allocation allowed)
__device__ __align__(16) float g_gate[8][4];
__device__ __align__(16) float g_A[8][16384];       // [b][r*2048+d]
__device__ __align__(16) float g_B[8][16384];       // [b][r*2048+o], pre-scaled by 2.0

union F2U { float2 f; unsigned long long u; };

__device__ __forceinline__ float2 ffma2(float2 a, float2 b, float2 c) {
    F2U ua, ub, uc, ur;
    ua.f = a; ub.f = b; uc.f = c;
    asm("fma.rn.f32x2 %0, %1, %2, %3;"
        : "=l"(ur.u) : "l"(ua.u), "l"(ub.u), "l"(uc.u));
    return ur.f;
}

// ---------------------------------------------------------------------------
// Kernel 1: gating MLP.  8 warps, warp w handles batch w.
// ---------------------------------------------------------------------------
__global__ void gate_kernel(const float* __restrict__ ctr,
                            const float* __restrict__ gamma,
                            const float* __restrict__ beta,
                            const float* __restrict__ W1,
                            const float* __restrict__ b1,
                            const float* __restrict__ W2,
                            const float* __restrict__ b2) {
    __shared__ float h_s[8][64];
    int w = threadIdx.x >> 5;
    int lane = threadIdx.x & 31;

    float c = ctr[w * 32 + lane];
    float mu = c;
    #pragma unroll
    for (int o = 16; o; o >>= 1) mu += __shfl_xor_sync(FULLMASK, mu, o);
    mu *= 0.03125f;
    float d = c - mu;
    float v = d * d;
    #pragma unroll
    for (int o = 16; o; o >>= 1) v += __shfl_xor_sync(FULLMASK, v, o);
    v *= 0.03125f;
    float z = d * rsqrtf(v + 1e-5f) * gamma[lane] + beta[lane];

    #pragma unroll
    for (int jj = 0; jj < 2; jj++) {
        int j = lane + (jj << 5);
        bool valid = (j < 60);
        float s = valid ? b1[j] : 0.f;
        for (int k = 0; k < 32; k++) {
            float zk = __shfl_sync(FULLMASK, z, k);
            if (valid) s += W1[j * 32 + k] * zk;
        }
        h_s[w][j] = valid ? fmaxf(s, 0.f) : 0.f;
    }
    __syncwarp();

    if (lane == 0) {
        float l[4], mx = -3.4e38f;
        #pragma unroll
        for (int i = 0; i < 4; i++) {
            float s = b2[i];
            for (int j = 0; j < 60; j++) s += W2[i * 60 + j] * h_s[w][j];
            l[i] = s;
            mx = fmaxf(mx, s);
        }
        float e[4], sum = 0.f;
        #pragma unroll
        for (int i = 0; i < 4; i++) { e[i] = expf(l[i] - mx); sum += e[i]; }
        float inv = 1.f / sum;
        #pragma unroll
        for (int i = 0; i < 4; i++) g_gate[w][i] = e[i] * inv;
    }
}

// ---------------------------------------------------------------------------
// Kernel 2: A = gate @ Wa^T, B = 2.0 * (gate @ Wb^T).
// ---------------------------------------------------------------------------
__global__ void ab_kernel(const float4* __restrict__ Wa,
                          const float4* __restrict__ Wb) {
    int i = blockIdx.x * blockDim.x + threadIdx.x;   // 0 .. 262143
    int half = i >> 17;                              // 0: A, 1: B
    int j = i & 131071;
    int b = j >> 14;
    int idx = j & 16383;
    float4 g = *(const float4*)&g_gate[b][0];
    float4 wv = half ? Wb[idx] : Wa[idx];
    float v = g.x * wv.x + g.y * wv.y + g.z * wv.z + g.w * wv.w;
    if (half) g_B[b][idx] = v * 2.0f;                // SCALING = 16/8 folded here
    else      g_A[b][idx] = v;
}

// ---------------------------------------------------------------------------
// Kernel 3 (fused): per block of 32 rows of batch b:
//   Phase 1: xa[row][r] = sum_d x[row][d]*A[b][r][d]  (A in 64KB smem,
//            4 rows/warp so each A LDS serves 4 rows, FFMA2, warp reduce)
//   Phase 2: out[row][o] = sum_r xa[row][r]*B[b][r][o] (B in registers,
//            xa broadcast from smem, coalesced float4 stores)
// ---------------------------------------------------------------------------
__global__ __launch_bounds__(256) void fused_kernel(const float* __restrict__ x,
                                                    float* __restrict__ out) {
    extern __shared__ float smem[];
    float4* A_s  = (float4*)smem;            // 4096 float4 = 64 KB
    float4* xa_s = (float4*)(smem + 16384);  // 64 float4 = 1 KB

    int b = blockIdx.y;
    int row0b = blockIdx.x * 32;

    const float4* Ag = (const float4*)&g_A[b][0];
    for (int i = threadIdx.x; i < 4096; i += 256) A_s[i] = Ag[i];
    __syncthreads();

    int warp = threadIdx.x >> 5;
    int lane = threadIdx.x & 31;
    int row0 = row0b + warp * 4;
    const float4* xrow = (const float4*)(x + (((size_t)b << 11) + row0) * 2048);

    float2 acc[4][8];
    #pragma unroll
    for (int j = 0; j < 4; j++)
        #pragma unroll
        for (int r = 0; r < 8; r++) acc[j][r] = make_float2(0.f, 0.f);

    #pragma unroll 2
    for (int i = 0; i < 16; i++) {
        int d4 = (i << 5) + lane;
        float4 xv0 = xrow[d4];
        float4 xv1 = xrow[512 + d4];
        float4 xv2 = xrow[1024 + d4];
        float4 xv3 = xrow[1536 + d4];
        #pragma unroll
        for (int r = 0; r < 8; r++) {
            float4 av = A_s[(r << 9) + d4];
            float2 alo = make_float2(av.x, av.y);
            float2 ahi = make_float2(av.z, av.w);
            acc[0][r] = ffma2(make_float2(xv0.x, xv0.y), alo, acc[0][r]);
            acc[0][r] = ffma2(make_float2(xv0.z, xv0.w), ahi, acc[0][r]);
            acc[1][r] = ffma2(make_float2(xv1.x, xv1.y), alo, acc[1][r]);
            acc[1][r] = ffma2(make_float2(xv1.z, xv1.w), ahi, acc[1][r]);
            acc[2][r] = ffma2(make_float2(xv2.x, xv2.y), alo, acc[2][r]);
            acc[2][r] = ffma2(make_float2(xv2.z, xv2.w), ahi, acc[2][r]);
            acc[3][r] = ffma2(make_float2(xv3.x, xv3.y), alo, acc[3][r]);
            acc[3][r] = ffma2(make_float2(xv3.z, xv3.w), ahi, acc[3][r]);
        }
    }

    #pragma unroll
    for (int j = 0; j < 4; j++) {
        float s[8];
        #pragma unroll
        for (int r = 0; r < 8; r++) {
            float v = acc[j][r].x + acc[j][r].y;
            #pragma unroll
            for (int o = 16; o; o >>= 1) v += __shfl_xor_sync(FULLMASK, v, o);
            s[r] = v;
        }
        if (lane == 0) {
            xa_s[(warp * 4 + j) * 2]     = make_float4(s[0], s[1], s[2], s[3]);
            xa_s[(warp * 4 + j) * 2 + 1] = make_float4(s[4], s[5], s[6], s[7]);
        }
    }

    // Phase 2: B into registers (independent of xa_s — overlaps the barrier)
    int t = threadIdx.x;
    const float4* Bg = (const float4*)&g_B[b][0];  // [8][512] float4
    float4 B0[8], B1[8];
    #pragma unroll
    for (int r = 0; r < 8; r++) {
        B0[r] = Bg[(r << 9) + t];
        B1[r] = Bg[(r << 9) + 256 + t];
    }
    __syncthreads();

    float4* orow = (float4*)(out + (((size_t)b << 11) + row0b) * 2048);
    #pragma unroll 2
    for (int row = 0; row < 32; row++) {
        float4 xa0 = xa_s[row * 2];
        float4 xa1 = xa_s[row * 2 + 1];
        float xr[8] = {xa0.x, xa0.y, xa0.z, xa0.w, xa1.x, xa1.y, xa1.z, xa1.w};
        float2 a0 = make_float2(0.f, 0.f), a1 = a0, a2 = a0, a3 = a0;
        #pragma unroll
        for (int r = 0; r < 8; r++) {
            float2 s = make_float2(xr[r], xr[r]);
            a0 = ffma2(s, make_float2(B0[r].x, B0[r].y), a0);
            a1 = ffma2(s, make_float2(B0[r].z, B0[r].w), a1);
            a2 = ffma2(s, make_float2(B1[r].x, B1[r].y), a2);
            a3 = ffma2(s, make_float2(B1[r].z, B1[r].w), a3);
        }
        orow[(row << 9) + t]       = make_float4(a0.x, a0.y, a1.x, a1.y);
        orow[(row << 9) + 256 + t] = make_float4(a2.x, a2.y, a3.x, a3.y);
    }
}

// ---------------------------------------------------------------------------
extern "C" void kernel_launch(void* const* d_in, const int* in_sizes, int n_in,
                              void* d_out, int out_size) {
    const float* x   = (const float*)d_in[0];
    const float* ctr = (const float*)d_in[1];
    const float* gam = (const float*)d_in[2];
    const float* bet = (const float*)d_in[3];
    const float* W1  = (const float*)d_in[4];
    const float* b1  = (const float*)d_in[5];
    const float* W2  = (const float*)d_in[6];
    const float* b2  = (const float*)d_in[7];
    const float* Wa  = (const float*)d_in[8];
    const float* Wb  = (const float*)d_in[9];
    float* out = (float*)d_out;

    cudaFuncSetAttribute(fused_kernel, cudaFuncAttributeMaxDynamicSharedMemorySize, 66560);

    gate_kernel<<<1, 256>>>(ctr, gam, bet, W1, b1, W2, b2);
    ab_kernel<<<1024, 256>>>((const float4*)Wa, (const float4*)Wb);
    fused_kernel<<<dim3(64, 8), 256, 66560>>>(x, out);
}

// round 7
// speedup vs baseline: 1.3995x; 1.1508x over previous
#include <cuda_runtime.h>
#include <math.h>

#define FULLMASK 0xffffffffu

// Scratch (device globals — no allocation allowed)
__device__ __align__(16) float g_A[8][16384];       // [b][r*2048+d]
__device__ __align__(16) float g_B[8][16384];       // [b][r*2048+o], pre-scaled by 2.0

union F2U { float2 f; unsigned long long u; };

__device__ __forceinline__ float2 ffma2(float2 a, float2 b, float2 c) {
    F2U ua, ub, uc, ur;
    ua.f = a; ub.f = b; uc.f = c;
    asm("fma.rn.f32x2 %0, %1, %2, %3;"
        : "=l"(ur.u) : "l"(ua.u), "l"(ub.u), "l"(uc.u));
    return ur.f;
}

// ---------------------------------------------------------------------------
// Kernel 1 (fused gate + A/B build).
// Grid (16 chunks, 8 batches), 256 threads.
// Warp 0 recomputes the gating MLP for batch b (redundant across the 16
// chunk-blocks — it's tiny and L2-resident). Meanwhile ALL threads prefetch
// their Wa/Wb rows (independent of gate), hiding the gate latency.
// After one __syncthreads, every thread finishes A = gate.Wa, B = 2*gate.Wb.
// ---------------------------------------------------------------------------
__global__ __launch_bounds__(256) void gab_kernel(
        const float* __restrict__ ctr,
        const float* __restrict__ gamma,
        const float* __restrict__ beta,
        const float* __restrict__ W1,
        const float* __restrict__ b1,
        const float* __restrict__ W2,
        const float* __restrict__ b2,
        const float4* __restrict__ Wa,
        const float4* __restrict__ Wb) {
    __shared__ float4 gate_s;
    int b = blockIdx.y;
    int chunk = blockIdx.x;           // 0..15
    int t = threadIdx.x;

    // --- Prefetch Wa/Wb for this chunk (independent of gate) ---
    // 16384 elements per batch / 16 chunks = 1024 / 256 threads = 4 each.
    int base = chunk * 1024;
    float4 wa[4], wb[4];
    #pragma unroll
    for (int k = 0; k < 4; k++) {
        int e = base + (k << 8) + t;
        wa[k] = Wa[e];
        wb[k] = Wb[e];
    }

    // --- Warp 0: gating MLP (LN -> Linear+ReLU -> Linear -> softmax) ---
    if (t < 32) {
        int lane = t;
        float c = ctr[b * 32 + lane];
        float mu = c;
        #pragma unroll
        for (int o = 16; o; o >>= 1) mu += __shfl_xor_sync(FULLMASK, mu, o);
        mu *= 0.03125f;
        float d = c - mu;
        float v = d * d;
        #pragma unroll
        for (int o = 16; o; o >>= 1) v += __shfl_xor_sync(FULLMASK, v, o);
        v *= 0.03125f;
        float z = d * rsqrtf(v + 1e-5f) * gamma[lane] + beta[lane];

        // h_j for j = lane and j = lane+32 (j < 60)
        int j1 = lane, j2 = lane + 32;
        bool v2 = (j2 < 60);
        float s1 = b1[j1];
        float s2 = v2 ? b1[j2] : 0.f;
        #pragma unroll
        for (int k = 0; k < 32; k++) {
            float zk = __shfl_sync(FULLMASK, z, k);
            s1 += W1[j1 * 32 + k] * zk;
            if (v2) s2 += W1[j2 * 32 + k] * zk;
        }
        float h1 = fmaxf(s1, 0.f);
        float h2 = v2 ? fmaxf(s2, 0.f) : 0.f;

        // layer 2: 4 outputs, lane-parallel partials over j, warp reduce
        float p[4];
        #pragma unroll
        for (int i = 0; i < 4; i++) {
            float s = W2[i * 60 + j1] * h1;
            if (v2) s += W2[i * 60 + j2] * h2;
            #pragma unroll
            for (int o = 16; o; o >>= 1) s += __shfl_xor_sync(FULLMASK, s, o);
            p[i] = s;
        }
        if (lane == 0) {
            float mx = fmaxf(fmaxf(p[0] + b2[0], p[1] + b2[1]),
                             fmaxf(p[2] + b2[2], p[3] + b2[3]));
            float e0 = expf(p[0] + b2[0] - mx);
            float e1 = expf(p[1] + b2[1] - mx);
            float e2 = expf(p[2] + b2[2] - mx);
            float e3 = expf(p[3] + b2[3] - mx);
            float inv = 1.f / (e0 + e1 + e2 + e3);
            gate_s = make_float4(e0 * inv, e1 * inv, e2 * inv, e3 * inv);
        }
    }
    __syncthreads();

    float4 g = gate_s;
    #pragma unroll
    for (int k = 0; k < 4; k++) {
        int e = base + (k << 8) + t;
        g_A[b][e] = g.x * wa[k].x + g.y * wa[k].y + g.z * wa[k].z + g.w * wa[k].w;
        g_B[b][e] = 2.0f * (g.x * wb[k].x + g.y * wb[k].y + g.z * wb[k].z + g.w * wb[k].w);
    }
}

// ---------------------------------------------------------------------------
// Kernel 2 (fused xa + out): per block of 32 rows of batch b:
//   Phase 1: xa[row][r] = sum_d x[row][d]*A[b][r][d]  (A in 64KB smem,
//            4 rows/warp so each A LDS serves 4 rows, FFMA2, warp reduce)
//   Phase 2: out[row][o] = sum_r xa[row][r]*B[b][r][o] (B in registers,
//            xa broadcast from smem, coalesced float4 stores)
// ---------------------------------------------------------------------------
__global__ __launch_bounds__(256) void fused_kernel(const float* __restrict__ x,
                                                    float* __restrict__ out) {
    extern __shared__ float smem[];
    float4* A_s  = (float4*)smem;            // 4096 float4 = 64 KB
    float4* xa_s = (float4*)(smem + 16384);  // 64 float4 = 1 KB

    int b = blockIdx.y;
    int row0b = blockIdx.x * 32;

    const float4* Ag = (const float4*)&g_A[b][0];
    for (int i = threadIdx.x; i < 4096; i += 256) A_s[i] = Ag[i];
    __syncthreads();

    int warp = threadIdx.x >> 5;
    int lane = threadIdx.x & 31;
    int row0 = row0b + warp * 4;
    const float4* xrow = (const float4*)(x + (((size_t)b << 11) + row0) * 2048);

    float2 acc[4][8];
    #pragma unroll
    for (int j = 0; j < 4; j++)
        #pragma unroll
        for (int r = 0; r < 8; r++) acc[j][r] = make_float2(0.f, 0.f);

    #pragma unroll 2
    for (int i = 0; i < 16; i++) {
        int d4 = (i << 5) + lane;
        float4 xv0 = xrow[d4];
        float4 xv1 = xrow[512 + d4];
        float4 xv2 = xrow[1024 + d4];
        float4 xv3 = xrow[1536 + d4];
        #pragma unroll
        for (int r = 0; r < 8; r++) {
            float4 av = A_s[(r << 9) + d4];
            float2 alo = make_float2(av.x, av.y);
            float2 ahi = make_float2(av.z, av.w);
            acc[0][r] = ffma2(make_float2(xv0.x, xv0.y), alo, acc[0][r]);
            acc[0][r] = ffma2(make_float2(xv0.z, xv0.w), ahi, acc[0][r]);
            acc[1][r] = ffma2(make_float2(xv1.x, xv1.y), alo, acc[1][r]);
            acc[1][r] = ffma2(make_float2(xv1.z, xv1.w), ahi, acc[1][r]);
            acc[2][r] = ffma2(make_float2(xv2.x, xv2.y), alo, acc[2][r]);
            acc[2][r] = ffma2(make_float2(xv2.z, xv2.w), ahi, acc[2][r]);
            acc[3][r] = ffma2(make_float2(xv3.x, xv3.y), alo, acc[3][r]);
            acc[3][r] = ffma2(make_float2(xv3.z, xv3.w), ahi, acc[3][r]);
        }
    }

    #pragma unroll
    for (int j = 0; j < 4; j++) {
        float s[8];
        #pragma unroll
        for (int r = 0; r < 8; r++) {
            float v = acc[j][r].x + acc[j][r].y;
            #pragma unroll
            for (int o = 16; o; o >>= 1) v += __shfl_xor_sync(FULLMASK, v, o);
            s[r] = v;
        }
        if (lane == 0) {
            xa_s[(warp * 4 + j) * 2]     = make_float4(s[0], s[1], s[2], s[3]);
            xa_s[(warp * 4 + j) * 2 + 1] = make_float4(s[4], s[5], s[6], s[7]);
        }
    }

    // Phase 2: B into registers (independent of xa_s — overlaps the barrier)
    int t = threadIdx.x;
    const float4* Bg = (const float4*)&g_B[b][0];  // [8][512] float4
    float4 B0[8], B1[8];
    #pragma unroll
    for (int r = 0; r < 8; r++) {
        B0[r] = Bg[(r << 9) + t];
        B1[r] = Bg[(r << 9) + 256 + t];
    }
    __syncthreads();

    float4* orow = (float4*)(out + (((size_t)b << 11) + row0b) * 2048);
    #pragma unroll 2
    for (int row = 0; row < 32; row++) {
        float4 xa0 = xa_s[row * 2];
        float4 xa1 = xa_s[row * 2 + 1];
        float xr[8] = {xa0.x, xa0.y, xa0.z, xa0.w, xa1.x, xa1.y, xa1.z, xa1.w};
        float2 a0 = make_float2(0.f, 0.f), a1 = a0, a2 = a0, a3 = a0;
        #pragma unroll
        for (int r = 0; r < 8; r++) {
            float2 s = make_float2(xr[r], xr[r]);
            a0 = ffma2(s, make_float2(B0[r].x, B0[r].y), a0);
            a1 = ffma2(s, make_float2(B0[r].z, B0[r].w), a1);
            a2 = ffma2(s, make_float2(B1[r].x, B1[r].y), a2);
            a3 = ffma2(s, make_float2(B1[r].z, B1[r].w), a3);
        }
        orow[(row << 9) + t]       = make_float4(a0.x, a0.y, a1.x, a1.y);
        orow[(row << 9) + 256 + t] = make_float4(a2.x, a2.y, a3.x, a3.y);
    }
}

// ---------------------------------------------------------------------------
extern "C" void kernel_launch(void* const* d_in, const int* in_sizes, int n_in,
                              void* d_out, int out_size) {
    const float* x   = (const float*)d_in[0];
    const float* ctr = (const float*)d_in[1];
    const float* gam = (const float*)d_in[2];
    const float* bet = (const float*)d_in[3];
    const float* W1  = (const float*)d_in[4];
    const float* b1  = (const float*)d_in[5];
    const float* W2  = (const float*)d_in[6];
    const float* b2  = (const float*)d_in[7];
    const float* Wa  = (const float*)d_in[8];
    const float* Wb  = (const float*)d_in[9];
    float* out = (float*)d_out;

    cudaFuncSetAttribute(fused_kernel, cudaFuncAttributeMaxDynamicSharedMemorySize, 66560);

    gab_kernel<<<dim3(16, 8), 256>>>(ctr, gam, bet, W1, b1, W2, b2,
                                     (const float4*)Wa, (const float4*)Wb);
    fused_kernel<<<dim3(64, 8), 256, 66560>>>(x, out);
}